// round 1
// baseline (speedup 1.0000x reference)
#include <cuda_runtime.h>
#include <cstdint>

#define Bdim  4
#define Sdim  1024
#define Hdim  1024
#define ENTn  16
#define INNER 64
#define NOUT  2048
#define NEGC  1.0e12f

// Scratch (allocation-free rule: __device__ globals)
__device__ float g_Q[Bdim*ENTn*Sdim*INNER];   // [b][h][s][d]
__device__ float g_K[Bdim*ENTn*Sdim*INNER];
__device__ float g_sin[Sdim*(INNER/2)];       // [s][j]
__device__ float g_cos[Sdim*(INNER/2)];

__device__ __forceinline__ uint32_t f2tf(float x){
    uint32_t u; asm("cvt.rna.tf32.f32 %0, %1;" : "=r"(u) : "f"(x)); return u;
}
__device__ __forceinline__ void cp16(void* s, const void* g){
    uint32_t sa = (uint32_t)__cvta_generic_to_shared(s);
    asm volatile("cp.async.cg.shared.global [%0], [%1], 16;" :: "r"(sa), "l"(g));
}
__device__ __forceinline__ void cp_commit(){ asm volatile("cp.async.commit_group;" ::: "memory"); }
template<int N> __device__ __forceinline__ void cp_wait(){
    asm volatile("cp.async.wait_group %0;" :: "n"(N) : "memory");
}
__device__ __forceinline__ void mma_tf32(float* c, const uint32_t* a, const uint32_t* b){
    asm volatile("mma.sync.aligned.m16n8k8.row.col.f32.tf32.tf32.f32 "
        "{%0,%1,%2,%3}, {%4,%5,%6,%7}, {%8,%9}, {%0,%1,%2,%3};"
        : "+f"(c[0]), "+f"(c[1]), "+f"(c[2]), "+f"(c[3])
        : "r"(a[0]), "r"(a[1]), "r"(a[2]), "r"(a[3]), "r"(b[0]), "r"(b[1]));
}

// ---------------------------------------------------------------------------
// Kernel T: RoPE sin/cos table, matching jax fp32 math:
// freq = 10000^(-2j/64) = 10000^(-j/32); ang = s*freq; sin/cos fp32.
// ---------------------------------------------------------------------------
__global__ void sincos_kernel(){
    int idx = blockIdx.x*blockDim.x + threadIdx.x;
    if (idx >= Sdim*32) return;
    int s = idx >> 5, j = idx & 31;
    float freq = powf(10000.0f, -(float)j * 0.03125f);
    float ang  = (float)s * freq;
    g_sin[idx] = sinf(ang);
    g_cos[idx] = cosf(ang);
}

// ---------------------------------------------------------------------------
// Kernel A: C = X@W + b, fused interleaved RoPE, scatter to g_Q/g_K.
// M=4096, N=2048, K=1024. CTA tile 128x64, BK=32, tf32 mma.sync, cp.async x2.
// SMEM strides chosen for conflict-free fragment LDS:
//   As [128][36]: bank = (36m+k)%32 = (4m+k)%32  -> bijective over (m:8, k:4)
//   Bs [32][72] : bank = (72k+n)%32 = (8k+n)%32  -> bijective over (k:4, n:8)
// ---------------------------------------------------------------------------
#define A_STR 36
#define B_STR 72
#define SMEM_A_BYTES ((2*128*A_STR + 2*32*B_STR)*4)

__global__ void __launch_bounds__(256) gemm1_rope_kernel(
    const float* __restrict__ X, const float* __restrict__ W,
    const float* __restrict__ bias)
{
    extern __shared__ float sm[];
    float* As = sm;                   // [2][128][A_STR]
    float* Bs = sm + 2*128*A_STR;     // [2][32][B_STR]
    const int tid  = threadIdx.x;
    const int lane = tid & 31, warp = tid >> 5;
    const int g = lane >> 2, tg = lane & 3;
    const int wm = warp >> 1, wn = warp & 1;
    const int mtile = blockIdx.y, ntile = blockIdx.x;
    const float* Xb = X + (size_t)mtile*128*Hdim;
    const float* Wb = W + ntile*64;

    float acc[2][4][4];
    #pragma unroll
    for (int a=0;a<2;a++)
        #pragma unroll
        for (int bq=0;bq<4;bq++)
            #pragma unroll
            for (int k=0;k<4;k++) acc[a][bq][k]=0.f;

    auto load_stage = [&](int ks, int bufsel){
        float* Ad = As + bufsel*128*A_STR;
        const int k0 = ks*32;
        #pragma unroll
        for (int i=0;i<4;i++){
            int t = tid + i*256;                 // 0..1023
            int row = t >> 3, kc = (t & 7) << 2; // 128 rows x 8 chunks
            cp16(Ad + row*A_STR + kc, Xb + (size_t)row*Hdim + k0 + kc);
        }
        float* Bd = Bs + bufsel*32*B_STR;
        #pragma unroll
        for (int i=0;i<2;i++){
            int t = tid + i*256;                  // 0..511
            int kr = t >> 4, nc = (t & 15) << 2;  // 32 rows x 16 chunks
            cp16(Bd + kr*B_STR + nc, Wb + (size_t)(k0+kr)*NOUT + nc);
        }
        cp_commit();
    };

    load_stage(0, 0);
    int buf = 0;
    for (int ks = 0; ks < 32; ks++){
        if (ks < 31){ load_stage(ks+1, buf^1); cp_wait<1>(); }
        else        { cp_wait<0>(); }
        __syncthreads();
        const float* Ab = As + buf*128*A_STR;
        const float* Bb = Bs + buf*32*B_STR;
        #pragma unroll
        for (int kk=0; kk<4; kk++){
            const int k0 = kk*8;
            uint32_t af[2][4], bf[4][2];
            #pragma unroll
            for (int mt=0; mt<2; mt++){
                int rb = wm*32 + mt*16;
                af[mt][0] = f2tf(Ab[(rb+g  )*A_STR + k0+tg  ]);
                af[mt][1] = f2tf(Ab[(rb+g+8)*A_STR + k0+tg  ]);
                af[mt][2] = f2tf(Ab[(rb+g  )*A_STR + k0+tg+4]);
                af[mt][3] = f2tf(Ab[(rb+g+8)*A_STR + k0+tg+4]);
            }
            #pragma unroll
            for (int nt=0; nt<4; nt++){
                int nb = wn*32 + nt*8 + g;
                bf[nt][0] = f2tf(Bb[(k0+tg  )*B_STR + nb]);
                bf[nt][1] = f2tf(Bb[(k0+tg+4)*B_STR + nb]);
            }
            #pragma unroll
            for (int mt=0; mt<2; mt++)
                #pragma unroll
                for (int nt=0; nt<4; nt++)
                    mma_tf32(acc[mt][nt], af[mt], bf[nt]);
        }
        __syncthreads();
        buf ^= 1;
    }

    // Epilogue: bias + RoPE (interleaved pairs are exactly the c0/c1 accum pair)
    #pragma unroll
    for (int nt=0; nt<4; nt++){
        const int n_loc = wn*32 + nt*8 + 2*tg;
        const int c = ntile*64 + n_loc;          // even
        const int h = c >> 7, r = c & 127;
        const int d = r & 63, jj = d >> 1;
        float* dst = (r < 64) ? g_Q : g_K;
        const float b0 = bias[c], b1 = bias[c+1];
        #pragma unroll
        for (int mt=0; mt<2; mt++){
            #pragma unroll
            for (int p=0; p<2; p++){
                int m = mtile*128 + wm*32 + mt*16 + g + p*8;
                int bb = m >> 10, s = m & 1023;
                float sv = g_sin[s*32 + jj], cv = g_cos[s*32 + jj];
                float v0 = acc[mt][nt][2*p]   + b0;
                float v1 = acc[mt][nt][2*p+1] + b1;
                float o0 = v0*cv - v1*sv;
                float o1 = v1*cv + v0*sv;
                int idx = ((bb*ENTn + h)*Sdim + s)*INNER + d;
                *reinterpret_cast<float2*>(dst + idx) = make_float2(o0, o1);
            }
        }
    }
}

// ---------------------------------------------------------------------------
// Kernel B: logits[z=(b,h)][m][n] = (Q[m]·K[n]) masked/scaled.
// Grid (ntile, mtile, z). 128x128 tiles.
// Strictly-lower tiles: exact constant, pure float4 streaming stores.
// Upper/diagonal: tf32 mma over d=64, pad/tril epilogue.
// ---------------------------------------------------------------------------
#define QK_STR 68
#define SMEM_B_BYTES (2*128*QK_STR*4)

__global__ void __launch_bounds__(256) attn_logits_kernel(
    const float* __restrict__ tok, float* __restrict__ out)
{
    const int ntile = blockIdx.x, mtile = blockIdx.y, z = blockIdx.z;
    const int bidx = z >> 4;
    const int tid = threadIdx.x;
    float* outb = out + ((size_t)z << 20);
    const float* padp = tok + bidx*Sdim + ntile*128;

    if (ntile < mtile){
        // fully-masked tile: value = (-(1-pad)*NEG - NEG)/8, exact vs reference
        const int n4 = (tid & 31) << 2;
        const int m0 = mtile*128 + (tid >> 5);
        float4 pv = *reinterpret_cast<const float4*>(padp + n4);
        float4 val;
        val.x = (-(1.0f - pv.x)*NEGC - NEGC)*0.125f;
        val.y = (-(1.0f - pv.y)*NEGC - NEGC)*0.125f;
        val.z = (-(1.0f - pv.z)*NEGC - NEGC)*0.125f;
        val.w = (-(1.0f - pv.w)*NEGC - NEGC)*0.125f;
        const int ncol = ntile*128 + n4;
        #pragma unroll
        for (int i=0;i<16;i++)
            *reinterpret_cast<float4*>(outb + ((size_t)(m0 + i*8) << 10) + ncol) = val;
        return;
    }

    extern __shared__ float sm[];
    float* Qs = sm;                // [128][QK_STR]
    float* Ks = sm + 128*QK_STR;   // [128][QK_STR]
    __shared__ float pad_s[128];
    if (tid < 128) pad_s[tid] = padp[tid];

    const float* Qg = g_Q + ((size_t)z*Sdim + (size_t)mtile*128)*INNER;
    const float* Kg = g_K + ((size_t)z*Sdim + (size_t)ntile*128)*INNER;
    #pragma unroll
    for (int i=0;i<8;i++){
        int t = tid + i*256;                   // 0..2047
        int row = t >> 4, ch = (t & 15) << 2;  // 128 rows x 16 chunks
        cp16(Qs + row*QK_STR + ch, Qg + row*INNER + ch);
        cp16(Ks + row*QK_STR + ch, Kg + row*INNER + ch);
    }
    cp_commit();
    cp_wait<0>();
    __syncthreads();

    const int lane = tid & 31, warp = tid >> 5;
    const int g = lane >> 2, tg = lane & 3;
    const int wm = warp >> 1, wn = warp & 1;   // 4 x 2 warps, warp tile 32x64

    float acc[2][8][4];
    #pragma unroll
    for (int a=0;a<2;a++)
        #pragma unroll
        for (int bq=0;bq<8;bq++)
            #pragma unroll
            for (int k=0;k<4;k++) acc[a][bq][k]=0.f;

    #pragma unroll
    for (int kk=0; kk<8; kk++){
        const int k0 = kk*8;
        uint32_t af[2][4], bf[8][2];
        #pragma unroll
        for (int mt=0; mt<2; mt++){
            int rb = wm*32 + mt*16;
            af[mt][0] = f2tf(Qs[(rb+g  )*QK_STR + k0+tg  ]);
            af[mt][1] = f2tf(Qs[(rb+g+8)*QK_STR + k0+tg  ]);
            af[mt][2] = f2tf(Qs[(rb+g  )*QK_STR + k0+tg+4]);
            af[mt][3] = f2tf(Qs[(rb+g+8)*QK_STR + k0+tg+4]);
        }
        #pragma unroll
        for (int nt=0; nt<8; nt++){
            int nb = wn*64 + nt*8 + g;
            bf[nt][0] = f2tf(Ks[nb*QK_STR + k0+tg  ]);
            bf[nt][1] = f2tf(Ks[nb*QK_STR + k0+tg+4]);
        }
        #pragma unroll
        for (int mt=0; mt<2; mt++)
            #pragma unroll
            for (int nt=0; nt<8; nt++)
                mma_tf32(acc[mt][nt], af[mt], bf[nt]);
    }

    #pragma unroll
    for (int mt=0; mt<2; mt++){
        #pragma unroll
        for (int nt=0; nt<8; nt++){
            const int n_loc = wn*64 + nt*8 + 2*tg;
            const int n = ntile*128 + n_loc;
            const float p0 = pad_s[n_loc], p1 = pad_s[n_loc+1];
            #pragma unroll
            for (int p=0; p<2; p++){
                const int m = mtile*128 + wm*32 + mt*16 + g + p*8;
                float v0 = acc[mt][nt][2*p]   * p0 - (1.0f - p0)*NEGC - ((n   < m) ? NEGC : 0.0f);
                float v1 = acc[mt][nt][2*p+1] * p1 - (1.0f - p1)*NEGC - ((n+1 < m) ? NEGC : 0.0f);
                *reinterpret_cast<float2*>(outb + ((size_t)m << 10) + n) =
                    make_float2(v0*0.125f, v1*0.125f);
            }
        }
    }
}

// ---------------------------------------------------------------------------
extern "C" void kernel_launch(void* const* d_in, const int* in_sizes, int n_in,
                              void* d_out, int out_size)
{
    const float* X    = (const float*)d_in[0];
    const float* W    = (const float*)d_in[1];
    const float* bias = (const float*)d_in[2];
    const float* tok  = (const float*)d_in[3];
    float* out = (float*)d_out;

    cudaFuncSetAttribute(gemm1_rope_kernel,
        cudaFuncAttributeMaxDynamicSharedMemorySize, SMEM_A_BYTES);
    cudaFuncSetAttribute(attn_logits_kernel,
        cudaFuncAttributeMaxDynamicSharedMemorySize, SMEM_B_BYTES);

    sincos_kernel<<<64, 512>>>();
    gemm1_rope_kernel<<<dim3(32, 32), 256, SMEM_A_BYTES>>>(X, W, bias);
    attn_logits_kernel<<<dim3(8, 8, 64), 256, SMEM_B_BYTES>>>(tok, out);
}